// round 15
// baseline (speedup 1.0000x reference)
#include <cuda_runtime.h>
#include <cuda_fp16.h>
#include <cstdint>
#include <cstddef>

// ---------------- constants ----------------
#define BATCH   16
#define TOK     4096
#define HID     1152
#define QKVN    3456
#define MLPN    4608
#define ADAN    6912
#define DH      72

#define OFF_QKV  0
#define OFF_PROJ 3981312
#define OFF_M1   5308416
#define OFF_M2   10616832
#define LSZ      15925248

// ---------------- scratch ----------------
__device__ float  g_h   [TOK * HID];
__device__ __half g_qkvh[TOK * QKVN];
__device__ __half g_x1h [TOK * HID];
__device__ __half g_aoh [TOK * HID];
__device__ __half g_mhh [TOK * MLPN];
__device__ __half g_wh  [2 * LSZ];
__device__ float  g_e1  [BATCH * HID];
__device__ float  g_scb [BATCH * HID];
__device__ float  g_mod [BATCH * ADAN];
__device__ float  g_fmod[BATCH * 2304];
__device__ float  g_part[36 * BATCH * ADAN];

// ---------------- helpers ----------------
__device__ __forceinline__ float silu_f(float x) { return x / (1.f + expf(-x)); }
__device__ __forceinline__ float gelu_f(float x) {
    float x3 = x * x * x;
    return 0.5f * x * (1.f + tanhf(0.7978845608028654f * (x + 0.044715f * x3)));
}
__device__ __forceinline__ uint32_t su32(const void* p) {
    uint32_t a;
    asm("{ .reg .u64 t; cvta.to.shared.u64 t, %1; cvt.u32.u64 %0, t; }" : "=r"(a) : "l"(p));
    return a;
}
__device__ __forceinline__ void cpa16(uint32_t dst, const void* src) {
    asm volatile("cp.async.cg.shared.global [%0], [%1], 16;" :: "r"(dst), "l"(src) : "memory");
}
__device__ __forceinline__ void cpa_commit() {
    asm volatile("cp.async.commit_group;" ::: "memory");
}
__device__ __forceinline__ void ldsm4(uint32_t* r, uint32_t a) {
    asm volatile("ldmatrix.sync.aligned.m8n8.x4.shared.b16 {%0,%1,%2,%3}, [%4];"
                 : "=r"(r[0]), "=r"(r[1]), "=r"(r[2]), "=r"(r[3]) : "r"(a));
}
__device__ __forceinline__ void ldsm4t(uint32_t* r, uint32_t a) {
    asm volatile("ldmatrix.sync.aligned.m8n8.x4.trans.shared.b16 {%0,%1,%2,%3}, [%4];"
                 : "=r"(r[0]), "=r"(r[1]), "=r"(r[2]), "=r"(r[3]) : "r"(a));
}
__device__ __forceinline__ void mma16816(float* d, const uint32_t* a, const uint32_t* b) {
    asm volatile("mma.sync.aligned.m16n8k16.row.col.f32.f16.f16.f32 "
                 "{%0,%1,%2,%3}, {%4,%5,%6,%7}, {%8,%9}, {%0,%1,%2,%3};"
                 : "+f"(d[0]), "+f"(d[1]), "+f"(d[2]), "+f"(d[3])
                 : "r"(a[0]), "r"(a[1]), "r"(a[2]), "r"(a[3]), "r"(b[0]), "r"(b[1]));
}

// ---------------- weight fp32 -> fp16 mirror (one layer per launch) ----------------
__global__ void __launch_bounds__(256) w2h_layer(
    const float* __restrict__ s_qkv, const float* __restrict__ s_prj,
    const float* __restrict__ s_m1,  const float* __restrict__ s_m2,
    __half* __restrict__ dst)
{
    int i = (blockIdx.x * 256 + threadIdx.x) * 4;
    if (i >= LSZ) return;
    const float* src; int off;
    if (i < OFF_PROJ)    { src = s_qkv; off = i; }
    else if (i < OFF_M1) { src = s_prj; off = i - OFF_PROJ; }
    else if (i < OFF_M2) { src = s_m1;  off = i - OFF_M1; }
    else                 { src = s_m2;  off = i - OFF_M2; }
    float4 v = *(const float4*)(src + off);
    __half2* d = (__half2*)(dst + i);
    d[0] = __floats2half2_rn(v.x, v.y);
    d[1] = __floats2half2_rn(v.z, v.w);
}

// ---------------- fp16 mma.sync GEMM, 128x128 CTA tile, k64 chunks, 2-stage ----------------
#define ABUF 18432u
#define BBUF 17408u
#define BS0  36864u
#define GSME 71680

template<int EPI>
__global__ void __launch_bounds__(256, 2) mma_gemm(
    const __half* __restrict__ A, const __half* __restrict__ Wh,
    const float* __restrict__ bias, void* __restrict__ Cv,
    const float* __restrict__ gate, int gstride, int N, int K)
{
    extern __shared__ char smc[];
    uint32_t smB = su32(smc);

    int tid = threadIdx.x;
    int m0 = blockIdx.y * 128, n0 = blockIdx.x * 128;
    int lane = tid & 31, wid = tid >> 5;
    int wm = wid >> 2, wn = wid & 3;
    int g = lane >> 2, q = lane & 3;
    int l15 = lane & 15, lhi = lane >> 4;

    const __half* Abase = A + (size_t)m0 * K;
    const __half* Wbase = Wh + n0;

    const int NC = K >> 6;
    float acc[4][4][4];
#pragma unroll
    for (int i = 0; i < 4; i++)
#pragma unroll
        for (int j = 0; j < 4; j++)
#pragma unroll
            for (int r = 0; r < 4; r++) acc[i][j][r] = 0.f;

#pragma unroll
    for (int i = 0; i < 4; i++) {
        int idx = tid + i * 256;
        int ar = idx >> 3, ac8 = (idx & 7) * 8;
        cpa16(smB + (uint32_t)(ar * 144 + ac8 * 2), Abase + (size_t)ar * K + ac8);
        int bk = idx >> 4, bn8 = (idx & 15) * 8;
        cpa16(smB + BS0 + (uint32_t)(bk * 272 + bn8 * 2), Wbase + (size_t)bk * N + bn8);
    }
    cpa_commit();

    for (int c = 0; c < NC; c++) {
        int buf = c & 1;
        if (c + 1 < NC) {
            int nb = buf ^ 1;
            const __half* Ab = Abase + (c + 1) * 64;
            const __half* Wb = Wbase + (size_t)((c + 1) * 64) * N;
#pragma unroll
            for (int i = 0; i < 4; i++) {
                int idx = tid + i * 256;
                int ar = idx >> 3, ac8 = (idx & 7) * 8;
                cpa16(smB + nb * ABUF + (uint32_t)(ar * 144 + ac8 * 2), Ab + (size_t)ar * K + ac8);
                int bk = idx >> 4, bn8 = (idx & 15) * 8;
                cpa16(smB + BS0 + nb * BBUF + (uint32_t)(bk * 272 + bn8 * 2), Wb + (size_t)bk * N + bn8);
            }
            cpa_commit();
            asm volatile("cp.async.wait_group 1;" ::: "memory");
        } else {
            asm volatile("cp.async.wait_group 0;" ::: "memory");
        }
        __syncthreads();

        uint32_t aB = smB + buf * ABUF;
        uint32_t bB = smB + BS0 + buf * BBUF;
#pragma unroll
        for (int ks = 0; ks < 4; ks++) {
            uint32_t af[4][4], bf[2][4];
#pragma unroll
            for (int mi = 0; mi < 4; mi++)
                ldsm4(af[mi], aB + (uint32_t)(((wm * 64 + mi * 16 + l15) * 72 + ks * 16 + lhi * 8) * 2));
#pragma unroll
            for (int nh = 0; nh < 2; nh++)
                ldsm4t(bf[nh], bB + (uint32_t)(((ks * 16 + l15) * 136 + wn * 32 + nh * 16 + lhi * 8) * 2));
#pragma unroll
            for (int mi = 0; mi < 4; mi++)
#pragma unroll
                for (int ni = 0; ni < 4; ni++)
                    mma16816(acc[mi][ni], af[mi], &bf[ni >> 1][(ni & 1) * 2]);
        }
        __syncthreads();
    }

    int bidx = m0 >> 8;
#pragma unroll
    for (int mi = 0; mi < 4; mi++) {
#pragma unroll
        for (int half = 0; half < 2; half++) {
            int row = m0 + wm * 64 + mi * 16 + g + half * 8;
#pragma unroll
            for (int ni = 0; ni < 4; ni++) {
                int col = n0 + wn * 32 + ni * 8 + 2 * q;
                float2 bv = *(const float2*)(bias + col);
                float v0 = acc[mi][ni][half * 2 + 0] + bv.x;
                float v1 = acc[mi][ni][half * 2 + 1] + bv.y;
                if (EPI == 0) {
                    __half* Crow = (__half*)Cv + (size_t)row * N;
                    *(__half2*)(Crow + col) = __floats2half2_rn(v0, v1);
                } else if (EPI == 1) {
                    __half* Crow = (__half*)Cv + (size_t)row * N;
                    *(__half2*)(Crow + col) = __floats2half2_rn(gelu_f(v0), gelu_f(v1));
                } else {
                    float* Crow = (float*)Cv + (size_t)row * N;
                    float2 gv = *(const float2*)(gate + (size_t)bidx * gstride + col);
                    float2 cv = *(float2*)(Crow + col);
                    cv.x += gv.x * v0; cv.y += gv.y * v1;
                    *(float2*)(Crow + col) = cv;
                }
            }
        }
    }
}

// ---------------- conditioning path: split-K (chunk 32) small-M GEMM ----------------
__global__ void __launch_bounds__(128) smk_part(
    const float* __restrict__ Abuf, const float* __restrict__ W, int N, int K)
{
    __shared__ float s[BATCH * 32];
    int tid = threadIdx.x;
    int kz = blockIdx.y;
    int j = blockIdx.x * 128 + tid;
    for (int i = tid; i < BATCH * 32; i += 128) {
        int b = i >> 5, kk = i & 31;
        s[i] = Abuf[b * K + kz * 32 + kk];
    }
    __syncthreads();
    float acc[BATCH];
#pragma unroll
    for (int b = 0; b < BATCH; b++) acc[b] = 0.f;
    const float* Wp = W + (size_t)(kz * 32) * N + j;
#pragma unroll
    for (int kk = 0; kk < 32; kk++) {
        float wv = Wp[(size_t)kk * N];
#pragma unroll
        for (int b = 0; b < BATCH; b++) acc[b] = fmaf(s[b * 32 + kk], wv, acc[b]);
    }
#pragma unroll
    for (int b = 0; b < BATCH; b++)
        g_part[(size_t)(kz * BATCH + b) * N + j] = acc[b];
}

// temb1 variant: sinusoid computed inline, chunk 16 of K=256
__global__ void __launch_bounds__(128) smk_part_t1(
    const float* __restrict__ tin, const float* __restrict__ W)
{
    __shared__ float s[BATCH * 16];
    int tid = threadIdx.x;
    int kz = blockIdx.y;     // 0..15
    int j = blockIdx.x * 128 + tid;
    for (int i = tid; i < BATCH * 16; i += 128) {
        int b = i >> 4, kk = i & 15;
        int gk = kz * 16 + kk;
        float fr = expf(-9.210340371976184f * (float)(gk & 127) / 128.f);
        float arg = tin[b] * fr;
        s[i] = (gk < 128) ? cosf(arg) : sinf(arg);
    }
    __syncthreads();
    float acc[BATCH];
#pragma unroll
    for (int b = 0; b < BATCH; b++) acc[b] = 0.f;
    const float* Wp = W + (size_t)(kz * 16) * HID + j;
#pragma unroll
    for (int kk = 0; kk < 16; kk++) {
        float wv = Wp[(size_t)kk * HID];
#pragma unroll
        for (int b = 0; b < BATCH; b++) acc[b] = fmaf(s[b * 16 + kk], wv, acc[b]);
    }
#pragma unroll
    for (int b = 0; b < BATCH; b++)
        g_part[(size_t)(kz * BATCH + b) * HID + j] = acc[b];
}

// EPI 0: out = sum + bias ; 1: silu(sum+bias) ; 2: silu(sum+bias+ytab[y[b]])
template<int EPI>
__global__ void __launch_bounds__(128) smk_reduce(
    const float* __restrict__ bias, const float* __restrict__ ytab,
    const int* __restrict__ y, float* __restrict__ out, int N, int KS)
{
    int j = blockIdx.x * 128 + threadIdx.x;
    int b = blockIdx.y;
    float acc = bias[j];
    for (int kz = 0; kz < KS; kz++)
        acc += g_part[(size_t)(kz * BATCH + b) * N + j];
    if (EPI == 1) acc = silu_f(acc);
    if (EPI == 2) acc = silu_f(acc + ytab[(size_t)y[b] * HID + j]);
    out[(size_t)b * N + j] = acc;
}

// ---------------- bicubic ----------------
__device__ __forceinline__ void bicubic_w(int i, float w[4]) {
    float s = (i + 0.5f) * 0.25f - 0.5f;
    float tot = 0.f;
#pragma unroll
    for (int j = 0; j < 4; j++) {
        float x = fabsf(s - (float)j);
        float v;
        if (x >= 2.f)      v = 0.f;
        else if (x >= 1.f) v = ((-0.5f * x + 2.5f) * x - 4.f) * x + 2.f;
        else               v = ((1.5f * x - 2.5f) * x) * x + 1.f;
        w[j] = v; tot += v;
    }
    float inv = 1.f / tot;
#pragma unroll
    for (int j = 0; j < 4; j++) w[j] *= inv;
}

// ---------------- patchify + pos-embed + layer-0 LN/modulate (float4 channels) ----------------
__global__ void __launch_bounds__(288) patchify_ln_kernel(
    const float* __restrict__ x, const float* __restrict__ pw,
    const float* __restrict__ pb, const float* __restrict__ pe,
    const float* __restrict__ mod0)
{
    int t = blockIdx.x;
    int b = t >> 8, gy = (t >> 4) & 15, gx = t & 15;
    int tid = threadIdx.x;
    int o4 = tid * 4;

    float xr[16];
#pragma unroll
    for (int ic = 0; ic < 4; ic++)
#pragma unroll
        for (int py = 0; py < 2; py++)
#pragma unroll
            for (int px = 0; px < 2; px++)
                xr[ic * 4 + py * 2 + px] =
                    x[(((size_t)b * 4 + ic) * 32 + (gy * 2 + py)) * 32 + gx * 2 + px];

    float wy[4], wx[4];
    bicubic_w(gy, wy); bicubic_w(gx, wx);
    float wyx[16];
#pragma unroll
    for (int jy = 0; jy < 4; jy++)
#pragma unroll
        for (int jx = 0; jx < 4; jx++) wyx[jy * 4 + jx] = wy[jy] * wx[jx];

    float a[4];
    {
        float4 pbv = *(const float4*)(pb + o4);
        a[0] = pbv.x; a[1] = pbv.y; a[2] = pbv.z; a[3] = pbv.w;
    }
#pragma unroll
    for (int r = 0; r < 4; r++) {
        const float* w = pw + (size_t)(o4 + r) * 16;
#pragma unroll
        for (int qq = 0; qq < 16; qq++) a[r] += xr[qq] * w[qq];
    }
#pragma unroll
    for (int qq = 0; qq < 16; qq++) {
        float4 pev = *(const float4*)(pe + (size_t)qq * HID + o4);
        float wq = wyx[qq];
        a[0] += wq * pev.x; a[1] += wq * pev.y; a[2] += wq * pev.z; a[3] += wq * pev.w;
    }
    *(float4*)(g_h + (size_t)t * HID + o4) = make_float4(a[0], a[1], a[2], a[3]);

    float s = a[0] + a[1] + a[2] + a[3];
    float s2 = a[0]*a[0] + a[1]*a[1] + a[2]*a[2] + a[3]*a[3];
#pragma unroll
    for (int o = 16; o > 0; o >>= 1) {
        s  += __shfl_xor_sync(0xffffffffu, s, o);
        s2 += __shfl_xor_sync(0xffffffffu, s2, o);
    }
    __shared__ float ws[9], ws2[9];
    int w9 = tid >> 5, lane = tid & 31;
    if (lane == 0) { ws[w9] = s; ws2[w9] = s2; }
    __syncthreads();
    if (tid == 0) {
        float aa = 0.f, a2 = 0.f;
        for (int i = 0; i < 9; i++) { aa += ws[i]; a2 += ws2[i]; }
        ws[0] = aa; ws2[0] = a2;
    }
    __syncthreads();
    float mean = ws[0] * (1.f / HID);
    float var  = ws2[0] * (1.f / HID) - mean * mean;
    float rstd = rsqrtf(var + 1e-6f);
    float4 sh4 = *(const float4*)(mod0 + (size_t)b * ADAN + o4);
    float4 sc4 = *(const float4*)(mod0 + (size_t)b * ADAN + HID + o4);
    float r0 = ((a[0] - mean) * rstd) * (1.f + sc4.x) + sh4.x;
    float r1 = ((a[1] - mean) * rstd) * (1.f + sc4.y) + sh4.y;
    float r2 = ((a[2] - mean) * rstd) * (1.f + sc4.z) + sh4.z;
    float r3 = ((a[3] - mean) * rstd) * (1.f + sc4.w) + sh4.w;
    __half2 h0 = __floats2half2_rn(r0, r1);
    __half2 h1 = __floats2half2_rn(r2, r3);
    uint2 u = make_uint2(*(uint32_t*)&h0, *(uint32_t*)&h1);
    *(uint2*)(g_x1h + (size_t)t * HID + o4) = u;
}

// ---------------- LN + adaLN modulate (float4 channels) ----------------
__global__ void __launch_bounds__(288) ln_mod_kernel(
    const float* __restrict__ sh, const float* __restrict__ sc, int mstride)
{
    int t = blockIdx.x;
    int b = t >> 8;
    int tid = threadIdx.x;
    int o4 = tid * 4;
    float4 v4 = *(const float4*)(g_h + (size_t)t * HID + o4);
    float s = v4.x + v4.y + v4.z + v4.w;
    float s2 = v4.x*v4.x + v4.y*v4.y + v4.z*v4.z + v4.w*v4.w;
#pragma unroll
    for (int o = 16; o > 0; o >>= 1) {
        s  += __shfl_xor_sync(0xffffffffu, s, o);
        s2 += __shfl_xor_sync(0xffffffffu, s2, o);
    }
    __shared__ float ws[9], ws2[9];
    int w = tid >> 5, lane = tid & 31;
    if (lane == 0) { ws[w] = s; ws2[w] = s2; }
    __syncthreads();
    if (tid == 0) {
        float a = 0.f, a2 = 0.f;
        for (int i = 0; i < 9; i++) { a += ws[i]; a2 += ws2[i]; }
        ws[0] = a; ws2[0] = a2;
    }
    __syncthreads();
    float mean = ws[0] * (1.f / HID);
    float var  = ws2[0] * (1.f / HID) - mean * mean;
    float rstd = rsqrtf(var + 1e-6f);
    float4 sh4 = *(const float4*)(sh + (size_t)b * mstride + o4);
    float4 sc4 = *(const float4*)(sc + (size_t)b * mstride + o4);
    float r0 = ((v4.x - mean) * rstd) * (1.f + sc4.x) + sh4.x;
    float r1 = ((v4.y - mean) * rstd) * (1.f + sc4.y) + sh4.y;
    float r2 = ((v4.z - mean) * rstd) * (1.f + sc4.z) + sh4.z;
    float r3 = ((v4.w - mean) * rstd) * (1.f + sc4.w) + sh4.w;
    __half2 h0 = __floats2half2_rn(r0, r1);
    __half2 h1 = __floats2half2_rn(r2, r3);
    uint2 u = make_uint2(*(uint32_t*)&h0, *(uint32_t*)&h1);
    *(uint2*)(g_x1h + (size_t)t * HID + o4) = u;
}

// ---------------- neighborhood attention (half2 both phases) ----------------
__global__ void __launch_bounds__(256) attn_kernel()
{
    int t = blockIdx.x;
    int b = t >> 8, i = (t >> 4) & 15, j = t & 15;
    int tid = threadIdx.x;
    int h = tid >> 4, p = tid & 15;

    __shared__ int   ntok[16];
    __shared__ float att[16][16];

    if (tid < 16) {
        int py = tid >> 2, px = tid & 3;
        int si = min(max(i - 2, 0), 12);
        int sj = min(max(j - 2, 0), 12);
        ntok[tid] = (b << 8) | ((si + py) << 4) | (sj + px);
    }
    __syncthreads();

    const __half2* q2 = (const __half2*)(g_qkvh + (size_t)t * QKVN + h * DH);
    const __half2* k2 = (const __half2*)(g_qkvh + (size_t)ntok[p] * QKVN + HID + h * DH);
    float acc = 0.f;
#pragma unroll 6
    for (int d = 0; d < DH / 2; d++) {
        float2 qa = __half22float2(q2[d]);
        float2 kb = __half22float2(k2[d]);
        acc = fmaf(qa.x, kb.x, acc);
        acc = fmaf(qa.y, kb.y, acc);
    }
    acc *= 0.11785113019775793f;

    float m = acc;
#pragma unroll
    for (int o = 8; o > 0; o >>= 1) m = fmaxf(m, __shfl_xor_sync(0xffffffffu, m, o, 16));
    float e = expf(acc - m);
    float s = e;
#pragma unroll
    for (int o = 8; o > 0; o >>= 1) s += __shfl_xor_sync(0xffffffffu, s, o, 16);
    att[h][p] = e / s;
    __syncthreads();

    for (int o2 = tid; o2 < HID / 2; o2 += 256) {
        int hh = o2 / (DH / 2);
        float sx = 0.f, sy = 0.f;
#pragma unroll
        for (int p2 = 0; p2 < 16; p2++) {
            __half2 vv = *(const __half2*)(g_qkvh + (size_t)ntok[p2] * QKVN + 2304 + 2 * o2);
            float2 vf = __half22float2(vv);
            float a = att[hh][p2];
            sx = fmaf(a, vf.x, sx);
            sy = fmaf(a, vf.y, sy);
        }
        *(__half2*)(g_aoh + (size_t)t * HID + 2 * o2) = __floats2half2_rn(sx, sy);
    }
}

// ---------------- final LN + modulate + linear + unpatchify (fused) ----------------
__global__ void __launch_bounds__(288) final2_kernel(
    const float* __restrict__ fmod, const float* __restrict__ flw,
    const float* __restrict__ flb, float* __restrict__ out)
{
    int t = blockIdx.x;
    int b = t >> 8, gy = (t >> 4) & 15, gx = t & 15;
    int tid = threadIdx.x;
    int o4 = tid * 4;

    __shared__ float xs[HID];
    __shared__ float part[9][32];
    __shared__ float ws[9], ws2[9];

    float4 v4 = *(const float4*)(g_h + (size_t)t * HID + o4);
    float s = v4.x + v4.y + v4.z + v4.w;
    float s2 = v4.x*v4.x + v4.y*v4.y + v4.z*v4.z + v4.w*v4.w;
#pragma unroll
    for (int o = 16; o > 0; o >>= 1) {
        s  += __shfl_xor_sync(0xffffffffu, s, o);
        s2 += __shfl_xor_sync(0xffffffffu, s2, o);
    }
    int w9 = tid >> 5, lane = tid & 31;
    if (lane == 0) { ws[w9] = s; ws2[w9] = s2; }
    __syncthreads();
    if (tid == 0) {
        float a = 0.f, a2 = 0.f;
        for (int i = 0; i < 9; i++) { a += ws[i]; a2 += ws2[i]; }
        ws[0] = a; ws2[0] = a2;
    }
    __syncthreads();
    float mean = ws[0] * (1.f / HID);
    float var  = ws2[0] * (1.f / HID) - mean * mean;
    float rstd = rsqrtf(var + 1e-6f);
    float4 sh4 = *(const float4*)(fmod + (size_t)b * 2304 + o4);
    float4 sc4 = *(const float4*)(fmod + (size_t)b * 2304 + HID + o4);
    xs[o4 + 0] = ((v4.x - mean) * rstd) * (1.f + sc4.x) + sh4.x;
    xs[o4 + 1] = ((v4.y - mean) * rstd) * (1.f + sc4.y) + sh4.y;
    xs[o4 + 2] = ((v4.z - mean) * rstd) * (1.f + sc4.z) + sh4.z;
    xs[o4 + 3] = ((v4.w - mean) * rstd) * (1.f + sc4.w) + sh4.w;
    __syncthreads();

    int col = tid & 31, seg = tid >> 5;     // 9 segments x 128 k
    float acc = 0.f;
    int k0 = seg * 128;
    for (int k = k0; k < k0 + 128; k++)
        acc += xs[k] * flw[(size_t)k * 32 + col];
    part[seg][col] = acc;
    __syncthreads();
    if (tid < 32) {
        float sum = flb[tid];
#pragma unroll
        for (int sg = 0; sg < 9; sg++) sum += part[sg][tid];
        int ch = tid & 7, pq = tid >> 3, p = pq >> 1, q = pq & 1;
        out[(((size_t)b * 8 + ch) * 32 + gy * 2 + p) * 32 + gx * 2 + q] = sum;
    }
}

// ---------------- launch ----------------
extern "C" void kernel_launch(void* const* d_in, const int* in_sizes, int n_in,
                              void* d_out, int out_size)
{
    const float* x    = (const float*)d_in[0];
    const float* tin  = (const float*)d_in[1];
    const int*   y    = (const int*)  d_in[2];
    const float* pos  = (const float*)d_in[3];
    const float* pw   = (const float*)d_in[4];
    const float* pb   = (const float*)d_in[5];
    const float* tw1  = (const float*)d_in[6];
    const float* tb1  = (const float*)d_in[7];
    const float* tw2  = (const float*)d_in[8];
    const float* tb2  = (const float*)d_in[9];
    const float* ytab = (const float*)d_in[10];
    const float* adaw = (const float*)d_in[11];
    const float* adab = (const float*)d_in[12];
    const float* qkvw = (const float*)d_in[13];
    const float* qkvb = (const float*)d_in[14];
    const float* prjw = (const float*)d_in[15];
    const float* prjb = (const float*)d_in[16];
    const float* m1w  = (const float*)d_in[17];
    const float* m1b  = (const float*)d_in[18];
    const float* m2w  = (const float*)d_in[19];
    const float* m2b  = (const float*)d_in[20];
    const float* flaw = (const float*)d_in[21];
    const float* flab = (const float*)d_in[22];
    const float* flw  = (const float*)d_in[23];
    const float* flb  = (const float*)d_in[24];
    float* out = (float*)d_out;

    float *p_h, *p_mod, *p_fmod, *p_e1, *p_scb;
    __half *p_qkvh, *p_x1h, *p_aoh, *p_mhh, *p_wh;
    cudaGetSymbolAddress((void**)&p_h,   g_h);
    cudaGetSymbolAddress((void**)&p_mod, g_mod);
    cudaGetSymbolAddress((void**)&p_fmod, g_fmod);
    cudaGetSymbolAddress((void**)&p_e1,  g_e1);
    cudaGetSymbolAddress((void**)&p_scb, g_scb);
    cudaGetSymbolAddress((void**)&p_qkvh, g_qkvh);
    cudaGetSymbolAddress((void**)&p_x1h, g_x1h);
    cudaGetSymbolAddress((void**)&p_aoh, g_aoh);
    cudaGetSymbolAddress((void**)&p_mhh, g_mhh);
    cudaGetSymbolAddress((void**)&p_wh,  g_wh);

    cudaFuncSetAttribute(mma_gemm<0>, cudaFuncAttributeMaxDynamicSharedMemorySize, GSME);
    cudaFuncSetAttribute(mma_gemm<1>, cudaFuncAttributeMaxDynamicSharedMemorySize, GSME);
    cudaFuncSetAttribute(mma_gemm<2>, cudaFuncAttributeMaxDynamicSharedMemorySize, GSME);

    // weight fp16 mirrors (one launch per layer)
    for (int l = 0; l < 2; l++) {
        w2h_layer<<<(LSZ / 4 + 255) / 256, 256>>>(
            qkvw + (size_t)l * HID * QKVN, prjw + (size_t)l * HID * HID,
            m1w + (size_t)l * HID * MLPN,  m2w + (size_t)l * MLPN * HID,
            p_wh + (size_t)l * LSZ);
    }

    // conditioning path
    smk_part_t1<<<dim3(HID / 128, 16), 128>>>(tin, tw1);
    smk_reduce<1><<<dim3(HID / 128, BATCH), 128>>>(tb1, nullptr, nullptr, p_e1, HID, 16);
    smk_part<<<dim3(HID / 128, 36), 128>>>(p_e1, tw2, HID, HID);
    smk_reduce<2><<<dim3(HID / 128, BATCH), 128>>>(tb2, ytab, y, p_scb, HID, 36);

    // layer-0 mod vectors must exist before fused patchify+LN
    smk_part<<<dim3(ADAN / 128, 36), 128>>>(p_scb, adaw, ADAN, HID);
    smk_reduce<0><<<dim3(ADAN / 128, BATCH), 128>>>(adab, nullptr, nullptr, p_mod, ADAN, 36);

    patchify_ln_kernel<<<TOK, 288>>>(x, pw, pb, pos, p_mod);

    for (int l = 0; l < 2; l++) {
        const __half* whL = p_wh + (size_t)l * LSZ;
        if (l > 0) {
            smk_part<<<dim3(ADAN / 128, 36), 128>>>(p_scb, adaw + (size_t)l * HID * ADAN, ADAN, HID);
            smk_reduce<0><<<dim3(ADAN / 128, BATCH), 128>>>(
                adab + (size_t)l * ADAN, nullptr, nullptr, p_mod, ADAN, 36);
            ln_mod_kernel<<<TOK, 288>>>(p_mod + 0, p_mod + HID, ADAN);
        }
        mma_gemm<0><<<dim3(QKVN / 128, TOK / 128), 256, GSME>>>(
            p_x1h, whL + OFF_QKV, qkvb + (size_t)l * QKVN, p_qkvh, nullptr, 0, QKVN, HID);
        attn_kernel<<<TOK, 256>>>();
        mma_gemm<2><<<dim3(HID / 128, TOK / 128), 256, GSME>>>(
            p_aoh, whL + OFF_PROJ, prjb + (size_t)l * HID, p_h, p_mod + 2 * HID, ADAN, HID, HID);

        ln_mod_kernel<<<TOK, 288>>>(p_mod + 3 * HID, p_mod + 4 * HID, ADAN);
        mma_gemm<1><<<dim3(MLPN / 128, TOK / 128), 256, GSME>>>(
            p_x1h, whL + OFF_M1, m1b + (size_t)l * MLPN, p_mhh, nullptr, 0, MLPN, HID);
        mma_gemm<2><<<dim3(HID / 128, TOK / 128), 256, GSME>>>(
            p_mhh, whL + OFF_M2, m2b + (size_t)l * HID, p_h, p_mod + 5 * HID, ADAN, HID, MLPN);
    }

    smk_part<<<dim3(2304 / 128, 36), 128>>>(p_scb, flaw, 2304, HID);
    smk_reduce<0><<<dim3(2304 / 128, BATCH), 128>>>(flab, nullptr, nullptr, p_fmod, 2304, 36);
    final2_kernel<<<TOK, 288>>>(p_fmod, flw, flb, out);

    (void)in_sizes; (void)n_in; (void)out_size;
}

// round 16
// speedup vs baseline: 1.0857x; 1.0857x over previous
#include <cuda_runtime.h>
#include <cuda_fp16.h>
#include <cstdint>
#include <cstddef>

// ---------------- constants ----------------
#define BATCH   16
#define TOK     4096
#define HID     1152
#define QKVN    3456
#define MLPN    4608
#define ADAN    6912
#define DH      72

#define OFF_QKV  0
#define OFF_PROJ 3981312
#define OFF_M1   5308416
#define OFF_M2   10616832
#define LSZ      15925248

// ---------------- scratch ----------------
__device__ float  g_h   [TOK * HID];
__device__ __half g_qkvh[TOK * QKVN];
__device__ __half g_x1h [TOK * HID];
__device__ __half g_aoh [TOK * HID];
__device__ __half g_mhh [TOK * MLPN];
__device__ __half g_wh  [2 * LSZ];
__device__ float  g_e1  [BATCH * HID];
__device__ float  g_scb [BATCH * HID];
__device__ float  g_mod [BATCH * ADAN];
__device__ float  g_fmod[BATCH * 2304];
__device__ float  g_part[36 * BATCH * ADAN];

// ---------------- helpers ----------------
__device__ __forceinline__ float silu_f(float x) { return x / (1.f + expf(-x)); }
__device__ __forceinline__ float gelu_f(float x) {
    float x3 = x * x * x;
    return 0.5f * x * (1.f + tanhf(0.7978845608028654f * (x + 0.044715f * x3)));
}
__device__ __forceinline__ uint32_t su32(const void* p) {
    uint32_t a;
    asm("{ .reg .u64 t; cvta.to.shared.u64 t, %1; cvt.u32.u64 %0, t; }" : "=r"(a) : "l"(p));
    return a;
}
__device__ __forceinline__ void cpa16(uint32_t dst, const void* src) {
    asm volatile("cp.async.cg.shared.global [%0], [%1], 16;" :: "r"(dst), "l"(src) : "memory");
}
__device__ __forceinline__ void cpa_commit() {
    asm volatile("cp.async.commit_group;" ::: "memory");
}
__device__ __forceinline__ void ldsm4(uint32_t* r, uint32_t a) {
    asm volatile("ldmatrix.sync.aligned.m8n8.x4.shared.b16 {%0,%1,%2,%3}, [%4];"
                 : "=r"(r[0]), "=r"(r[1]), "=r"(r[2]), "=r"(r[3]) : "r"(a));
}
__device__ __forceinline__ void ldsm4t(uint32_t* r, uint32_t a) {
    asm volatile("ldmatrix.sync.aligned.m8n8.x4.trans.shared.b16 {%0,%1,%2,%3}, [%4];"
                 : "=r"(r[0]), "=r"(r[1]), "=r"(r[2]), "=r"(r[3]) : "r"(a));
}
__device__ __forceinline__ void mma16816(float* d, const uint32_t* a, const uint32_t* b) {
    asm volatile("mma.sync.aligned.m16n8k16.row.col.f32.f16.f16.f32 "
                 "{%0,%1,%2,%3}, {%4,%5,%6,%7}, {%8,%9}, {%0,%1,%2,%3};"
                 : "+f"(d[0]), "+f"(d[1]), "+f"(d[2]), "+f"(d[3])
                 : "r"(a[0]), "r"(a[1]), "r"(a[2]), "r"(a[3]), "r"(b[0]), "r"(b[1]));
}

// ---------------- weight fp32 -> fp16 mirror (one layer per launch) ----------------
__global__ void __launch_bounds__(256) w2h_layer(
    const float* __restrict__ s_qkv, const float* __restrict__ s_prj,
    const float* __restrict__ s_m1,  const float* __restrict__ s_m2,
    __half* __restrict__ dst)
{
    int i = (blockIdx.x * 256 + threadIdx.x) * 4;
    if (i >= LSZ) return;
    const float* src; int off;
    if (i < OFF_PROJ)    { src = s_qkv; off = i; }
    else if (i < OFF_M1) { src = s_prj; off = i - OFF_PROJ; }
    else if (i < OFF_M2) { src = s_m1;  off = i - OFF_M1; }
    else                 { src = s_m2;  off = i - OFF_M2; }
    float4 v = *(const float4*)(src + off);
    __half2* d = (__half2*)(dst + i);
    d[0] = __floats2half2_rn(v.x, v.y);
    d[1] = __floats2half2_rn(v.z, v.w);
}

// ---------------- fp16 mma.sync GEMM, 128x128 CTA tile, k64 chunks, 2-stage ----------------
#define ABUF 18432u
#define BBUF 17408u
#define BS0  36864u
#define GSME 71680

template<int EPI>
__global__ void __launch_bounds__(256, 2) mma_gemm(
    const __half* __restrict__ A, const __half* __restrict__ Wh,
    const float* __restrict__ bias, void* __restrict__ Cv,
    const float* __restrict__ gate, int gstride, int N, int K)
{
    extern __shared__ char smc[];
    uint32_t smB = su32(smc);

    int tid = threadIdx.x;
    int m0 = blockIdx.y * 128, n0 = blockIdx.x * 128;
    int lane = tid & 31, wid = tid >> 5;
    int wm = wid >> 2, wn = wid & 3;
    int g = lane >> 2, q = lane & 3;
    int l15 = lane & 15, lhi = lane >> 4;

    const __half* Abase = A + (size_t)m0 * K;
    const __half* Wbase = Wh + n0;

    const int NC = K >> 6;
    float acc[4][4][4];
#pragma unroll
    for (int i = 0; i < 4; i++)
#pragma unroll
        for (int j = 0; j < 4; j++)
#pragma unroll
            for (int r = 0; r < 4; r++) acc[i][j][r] = 0.f;

#pragma unroll
    for (int i = 0; i < 4; i++) {
        int idx = tid + i * 256;
        int ar = idx >> 3, ac8 = (idx & 7) * 8;
        cpa16(smB + (uint32_t)(ar * 144 + ac8 * 2), Abase + (size_t)ar * K + ac8);
        int bk = idx >> 4, bn8 = (idx & 15) * 8;
        cpa16(smB + BS0 + (uint32_t)(bk * 272 + bn8 * 2), Wbase + (size_t)bk * N + bn8);
    }
    cpa_commit();

    for (int c = 0; c < NC; c++) {
        int buf = c & 1;
        if (c + 1 < NC) {
            int nb = buf ^ 1;
            const __half* Ab = Abase + (c + 1) * 64;
            const __half* Wb = Wbase + (size_t)((c + 1) * 64) * N;
#pragma unroll
            for (int i = 0; i < 4; i++) {
                int idx = tid + i * 256;
                int ar = idx >> 3, ac8 = (idx & 7) * 8;
                cpa16(smB + nb * ABUF + (uint32_t)(ar * 144 + ac8 * 2), Ab + (size_t)ar * K + ac8);
                int bk = idx >> 4, bn8 = (idx & 15) * 8;
                cpa16(smB + BS0 + nb * BBUF + (uint32_t)(bk * 272 + bn8 * 2), Wb + (size_t)bk * N + bn8);
            }
            cpa_commit();
            asm volatile("cp.async.wait_group 1;" ::: "memory");
        } else {
            asm volatile("cp.async.wait_group 0;" ::: "memory");
        }
        __syncthreads();

        uint32_t aB = smB + buf * ABUF;
        uint32_t bB = smB + BS0 + buf * BBUF;
#pragma unroll
        for (int ks = 0; ks < 4; ks++) {
            uint32_t af[4][4], bf[2][4];
#pragma unroll
            for (int mi = 0; mi < 4; mi++)
                ldsm4(af[mi], aB + (uint32_t)(((wm * 64 + mi * 16 + l15) * 72 + ks * 16 + lhi * 8) * 2));
#pragma unroll
            for (int nh = 0; nh < 2; nh++)
                ldsm4t(bf[nh], bB + (uint32_t)(((ks * 16 + l15) * 136 + wn * 32 + nh * 16 + lhi * 8) * 2));
#pragma unroll
            for (int mi = 0; mi < 4; mi++)
#pragma unroll
                for (int ni = 0; ni < 4; ni++)
                    mma16816(acc[mi][ni], af[mi], &bf[ni >> 1][(ni & 1) * 2]);
        }
        __syncthreads();
    }

    int bidx = m0 >> 8;
#pragma unroll
    for (int mi = 0; mi < 4; mi++) {
#pragma unroll
        for (int half = 0; half < 2; half++) {
            int row = m0 + wm * 64 + mi * 16 + g + half * 8;
#pragma unroll
            for (int ni = 0; ni < 4; ni++) {
                int col = n0 + wn * 32 + ni * 8 + 2 * q;
                float2 bv = *(const float2*)(bias + col);
                float v0 = acc[mi][ni][half * 2 + 0] + bv.x;
                float v1 = acc[mi][ni][half * 2 + 1] + bv.y;
                if (EPI == 0) {
                    __half* Crow = (__half*)Cv + (size_t)row * N;
                    *(__half2*)(Crow + col) = __floats2half2_rn(v0, v1);
                } else if (EPI == 1) {
                    __half* Crow = (__half*)Cv + (size_t)row * N;
                    *(__half2*)(Crow + col) = __floats2half2_rn(gelu_f(v0), gelu_f(v1));
                } else {
                    float* Crow = (float*)Cv + (size_t)row * N;
                    float2 gv = *(const float2*)(gate + (size_t)bidx * gstride + col);
                    float2 cv = *(float2*)(Crow + col);
                    cv.x += gv.x * v0; cv.y += gv.y * v1;
                    *(float2*)(Crow + col) = cv;
                }
            }
        }
    }
}

// ---------------- conditioning path: split-K (chunk 32) small-M GEMM ----------------
__global__ void __launch_bounds__(128) smk_part(
    const float* __restrict__ Abuf, const float* __restrict__ W, int N, int K)
{
    __shared__ float s[BATCH * 32];
    int tid = threadIdx.x;
    int kz = blockIdx.y;
    int j = blockIdx.x * 128 + tid;
    for (int i = tid; i < BATCH * 32; i += 128) {
        int b = i >> 5, kk = i & 31;
        s[i] = Abuf[b * K + kz * 32 + kk];
    }
    __syncthreads();
    float acc[BATCH];
#pragma unroll
    for (int b = 0; b < BATCH; b++) acc[b] = 0.f;
    const float* Wp = W + (size_t)(kz * 32) * N + j;
#pragma unroll
    for (int kk = 0; kk < 32; kk++) {
        float wv = Wp[(size_t)kk * N];
#pragma unroll
        for (int b = 0; b < BATCH; b++) acc[b] = fmaf(s[b * 32 + kk], wv, acc[b]);
    }
#pragma unroll
    for (int b = 0; b < BATCH; b++)
        g_part[(size_t)(kz * BATCH + b) * N + j] = acc[b];
}

// temb1 variant: sinusoid computed inline, chunk 16 of K=256
__global__ void __launch_bounds__(128) smk_part_t1(
    const float* __restrict__ tin, const float* __restrict__ W)
{
    __shared__ float s[BATCH * 16];
    int tid = threadIdx.x;
    int kz = blockIdx.y;     // 0..15
    int j = blockIdx.x * 128 + tid;
    for (int i = tid; i < BATCH * 16; i += 128) {
        int b = i >> 4, kk = i & 15;
        int gk = kz * 16 + kk;
        float fr = expf(-9.210340371976184f * (float)(gk & 127) / 128.f);
        float arg = tin[b] * fr;
        s[i] = (gk < 128) ? cosf(arg) : sinf(arg);
    }
    __syncthreads();
    float acc[BATCH];
#pragma unroll
    for (int b = 0; b < BATCH; b++) acc[b] = 0.f;
    const float* Wp = W + (size_t)(kz * 16) * HID + j;
#pragma unroll
    for (int kk = 0; kk < 16; kk++) {
        float wv = Wp[(size_t)kk * HID];
#pragma unroll
        for (int b = 0; b < BATCH; b++) acc[b] = fmaf(s[b * 16 + kk], wv, acc[b]);
    }
#pragma unroll
    for (int b = 0; b < BATCH; b++)
        g_part[(size_t)(kz * BATCH + b) * HID + j] = acc[b];
}

// EPI 0: out = sum + bias ; 1: silu(sum+bias) ; 2: silu(sum+bias+ytab[y[b]])
template<int EPI>
__global__ void __launch_bounds__(128) smk_reduce(
    const float* __restrict__ bias, const float* __restrict__ ytab,
    const int* __restrict__ y, float* __restrict__ out, int N, int KS)
{
    int j = blockIdx.x * 128 + threadIdx.x;
    int b = blockIdx.y;
    float acc = bias[j];
    for (int kz = 0; kz < KS; kz++)
        acc += g_part[(size_t)(kz * BATCH + b) * N + j];
    if (EPI == 1) acc = silu_f(acc);
    if (EPI == 2) acc = silu_f(acc + ytab[(size_t)y[b] * HID + j]);
    out[(size_t)b * N + j] = acc;
}

// ---------------- bicubic ----------------
__device__ __forceinline__ void bicubic_w(int i, float w[4]) {
    float s = (i + 0.5f) * 0.25f - 0.5f;
    float tot = 0.f;
#pragma unroll
    for (int j = 0; j < 4; j++) {
        float x = fabsf(s - (float)j);
        float v;
        if (x >= 2.f)      v = 0.f;
        else if (x >= 1.f) v = ((-0.5f * x + 2.5f) * x - 4.f) * x + 2.f;
        else               v = ((1.5f * x - 2.5f) * x) * x + 1.f;
        w[j] = v; tot += v;
    }
    float inv = 1.f / tot;
#pragma unroll
    for (int j = 0; j < 4; j++) w[j] *= inv;
}

// ---------------- patchify + pos-embed + layer-0 LN/modulate (round-13 form) ----------------
__global__ void __launch_bounds__(288) patchify_ln_kernel(
    const float* __restrict__ x, const float* __restrict__ pw,
    const float* __restrict__ pb, const float* __restrict__ pe,
    const float* __restrict__ mod0)
{
    int t = blockIdx.x;
    int b = t >> 8, gy = (t >> 4) & 15, gx = t & 15;
    int tid = threadIdx.x;

    float xr[16];
#pragma unroll
    for (int ic = 0; ic < 4; ic++)
#pragma unroll
        for (int py = 0; py < 2; py++)
#pragma unroll
            for (int px = 0; px < 2; px++)
                xr[ic * 4 + py * 2 + px] =
                    x[(((size_t)b * 4 + ic) * 32 + (gy * 2 + py)) * 32 + gx * 2 + px];

    float wy[4], wx[4];
    bicubic_w(gy, wy); bicubic_w(gx, wx);
    float wyx[16];
#pragma unroll
    for (int jy = 0; jy < 4; jy++)
#pragma unroll
        for (int jx = 0; jx < 4; jx++) wyx[jy * 4 + jx] = wy[jy] * wx[jx];

    float v[4]; float s = 0.f, s2 = 0.f;
#pragma unroll
    for (int k = 0; k < 4; k++) {
        int o = tid + k * 288;
        float a = pb[o];
        const float* w = pw + (size_t)o * 16;
#pragma unroll
        for (int qq = 0; qq < 16; qq++) a += xr[qq] * w[qq];
        float p = 0.f;
#pragma unroll
        for (int qq = 0; qq < 16; qq++) p += wyx[qq] * pe[(size_t)qq * HID + o];
        float hv = a + p;
        g_h[(size_t)t * HID + o] = hv;
        v[k] = hv; s += hv; s2 += hv * hv;
    }

#pragma unroll
    for (int o = 16; o > 0; o >>= 1) {
        s  += __shfl_xor_sync(0xffffffffu, s, o);
        s2 += __shfl_xor_sync(0xffffffffu, s2, o);
    }
    __shared__ float ws[9], ws2[9];
    int w9 = tid >> 5, lane = tid & 31;
    if (lane == 0) { ws[w9] = s; ws2[w9] = s2; }
    __syncthreads();
    if (tid == 0) {
        float a = 0.f, a2 = 0.f;
        for (int i = 0; i < 9; i++) { a += ws[i]; a2 += ws2[i]; }
        ws[0] = a; ws2[0] = a2;
    }
    __syncthreads();
    float mean = ws[0] * (1.f / HID);
    float var  = ws2[0] * (1.f / HID) - mean * mean;
    float rstd = rsqrtf(var + 1e-6f);
    const float* shr = mod0 + (size_t)b * ADAN;
    const float* scr = shr + HID;
    __half* orow = g_x1h + (size_t)t * HID;
#pragma unroll
    for (int k = 0; k < 4; k++) {
        int j = tid + k * 288;
        float xm = (v[k] - mean) * rstd;
        orow[j] = __float2half(xm * (1.f + scr[j]) + shr[j]);
    }
}

// ---------------- LN + adaLN modulate (round-13 block form) ----------------
__global__ void __launch_bounds__(288) ln_mod_kernel(
    const float* __restrict__ sh, const float* __restrict__ sc, int mstride)
{
    int t = blockIdx.x;
    int b = t >> 8;
    int tid = threadIdx.x;
    const float* row = g_h + (size_t)t * HID;
    float v[4]; float s = 0.f, s2 = 0.f;
#pragma unroll
    for (int k = 0; k < 4; k++) {
        float xv = row[tid + k * 288];
        v[k] = xv; s += xv; s2 += xv * xv;
    }
#pragma unroll
    for (int o = 16; o > 0; o >>= 1) {
        s  += __shfl_xor_sync(0xffffffffu, s, o);
        s2 += __shfl_xor_sync(0xffffffffu, s2, o);
    }
    __shared__ float ws[9], ws2[9];
    int w = tid >> 5, lane = tid & 31;
    if (lane == 0) { ws[w] = s; ws2[w] = s2; }
    __syncthreads();
    if (tid == 0) {
        float a = 0.f, a2 = 0.f;
        for (int i = 0; i < 9; i++) { a += ws[i]; a2 += ws2[i]; }
        ws[0] = a; ws2[0] = a2;
    }
    __syncthreads();
    float mean = ws[0] * (1.f / HID);
    float var  = ws2[0] * (1.f / HID) - mean * mean;
    float rstd = rsqrtf(var + 1e-6f);
    const float* shr = sh + (size_t)b * mstride;
    const float* scr = sc + (size_t)b * mstride;
    __half* orow = g_x1h + (size_t)t * HID;
#pragma unroll
    for (int k = 0; k < 4; k++) {
        int j = tid + k * 288;
        float xm = (v[k] - mean) * rstd;
        orow[j] = __float2half(xm * (1.f + scr[j]) + shr[j]);
    }
}

// ---------------- neighborhood attention (half2 both phases) ----------------
__global__ void __launch_bounds__(256) attn_kernel()
{
    int t = blockIdx.x;
    int b = t >> 8, i = (t >> 4) & 15, j = t & 15;
    int tid = threadIdx.x;
    int h = tid >> 4, p = tid & 15;

    __shared__ int   ntok[16];
    __shared__ float att[16][16];

    if (tid < 16) {
        int py = tid >> 2, px = tid & 3;
        int si = min(max(i - 2, 0), 12);
        int sj = min(max(j - 2, 0), 12);
        ntok[tid] = (b << 8) | ((si + py) << 4) | (sj + px);
    }
    __syncthreads();

    const __half2* q2 = (const __half2*)(g_qkvh + (size_t)t * QKVN + h * DH);
    const __half2* k2 = (const __half2*)(g_qkvh + (size_t)ntok[p] * QKVN + HID + h * DH);
    float acc = 0.f;
#pragma unroll 6
    for (int d = 0; d < DH / 2; d++) {
        float2 qa = __half22float2(q2[d]);
        float2 kb = __half22float2(k2[d]);
        acc = fmaf(qa.x, kb.x, acc);
        acc = fmaf(qa.y, kb.y, acc);
    }
    acc *= 0.11785113019775793f;

    float m = acc;
#pragma unroll
    for (int o = 8; o > 0; o >>= 1) m = fmaxf(m, __shfl_xor_sync(0xffffffffu, m, o, 16));
    float e = expf(acc - m);
    float s = e;
#pragma unroll
    for (int o = 8; o > 0; o >>= 1) s += __shfl_xor_sync(0xffffffffu, s, o, 16);
    att[h][p] = e / s;
    __syncthreads();

    for (int o2 = tid; o2 < HID / 2; o2 += 256) {
        int hh = o2 / (DH / 2);
        float sx = 0.f, sy = 0.f;
#pragma unroll
        for (int p2 = 0; p2 < 16; p2++) {
            __half2 vv = *(const __half2*)(g_qkvh + (size_t)ntok[p2] * QKVN + 2304 + 2 * o2);
            float2 vf = __half22float2(vv);
            float a = att[hh][p2];
            sx = fmaf(a, vf.x, sx);
            sy = fmaf(a, vf.y, sy);
        }
        *(__half2*)(g_aoh + (size_t)t * HID + 2 * o2) = __floats2half2_rn(sx, sy);
    }
}

// ---------------- final LN + modulate + linear + unpatchify (fused, fp32) ----------------
__global__ void __launch_bounds__(288) final2_kernel(
    const float* __restrict__ fmod, const float* __restrict__ flw,
    const float* __restrict__ flb, float* __restrict__ out)
{
    int t = blockIdx.x;
    int b = t >> 8, gy = (t >> 4) & 15, gx = t & 15;
    int tid = threadIdx.x;
    int o4 = tid * 4;

    __shared__ float xs[HID];
    __shared__ float part[9][32];
    __shared__ float ws[9], ws2[9];

    float4 v4 = *(const float4*)(g_h + (size_t)t * HID + o4);
    float s = v4.x + v4.y + v4.z + v4.w;
    float s2 = v4.x*v4.x + v4.y*v4.y + v4.z*v4.z + v4.w*v4.w;
#pragma unroll
    for (int o = 16; o > 0; o >>= 1) {
        s  += __shfl_xor_sync(0xffffffffu, s, o);
        s2 += __shfl_xor_sync(0xffffffffu, s2, o);
    }
    int w9 = tid >> 5, lane = tid & 31;
    if (lane == 0) { ws[w9] = s; ws2[w9] = s2; }
    __syncthreads();
    if (tid == 0) {
        float a = 0.f, a2 = 0.f;
        for (int i = 0; i < 9; i++) { a += ws[i]; a2 += ws2[i]; }
        ws[0] = a; ws2[0] = a2;
    }
    __syncthreads();
    float mean = ws[0] * (1.f / HID);
    float var  = ws2[0] * (1.f / HID) - mean * mean;
    float rstd = rsqrtf(var + 1e-6f);
    float4 sh4 = *(const float4*)(fmod + (size_t)b * 2304 + o4);
    float4 sc4 = *(const float4*)(fmod + (size_t)b * 2304 + HID + o4);
    xs[o4 + 0] = ((v4.x - mean) * rstd) * (1.f + sc4.x) + sh4.x;
    xs[o4 + 1] = ((v4.y - mean) * rstd) * (1.f + sc4.y) + sh4.y;
    xs[o4 + 2] = ((v4.z - mean) * rstd) * (1.f + sc4.z) + sh4.z;
    xs[o4 + 3] = ((v4.w - mean) * rstd) * (1.f + sc4.w) + sh4.w;
    __syncthreads();

    int col = tid & 31, seg = tid >> 5;     // 9 segments x 128 k
    float acc = 0.f;
    int k0 = seg * 128;
    for (int k = k0; k < k0 + 128; k++)
        acc += xs[k] * flw[(size_t)k * 32 + col];
    part[seg][col] = acc;
    __syncthreads();
    if (tid < 32) {
        float sum = flb[tid];
#pragma unroll
        for (int sg = 0; sg < 9; sg++) sum += part[sg][tid];
        int ch = tid & 7, pq = tid >> 3, p = pq >> 1, q = pq & 1;
        out[(((size_t)b * 8 + ch) * 32 + gy * 2 + p) * 32 + gx * 2 + q] = sum;
    }
}

// ---------------- launch ----------------
extern "C" void kernel_launch(void* const* d_in, const int* in_sizes, int n_in,
                              void* d_out, int out_size)
{
    const float* x    = (const float*)d_in[0];
    const float* tin  = (const float*)d_in[1];
    const int*   y    = (const int*)  d_in[2];
    const float* pos  = (const float*)d_in[3];
    const float* pw   = (const float*)d_in[4];
    const float* pb   = (const float*)d_in[5];
    const float* tw1  = (const float*)d_in[6];
    const float* tb1  = (const float*)d_in[7];
    const float* tw2  = (const float*)d_in[8];
    const float* tb2  = (const float*)d_in[9];
    const float* ytab = (const float*)d_in[10];
    const float* adaw = (const float*)d_in[11];
    const float* adab = (const float*)d_in[12];
    const float* qkvw = (const float*)d_in[13];
    const float* qkvb = (const float*)d_in[14];
    const float* prjw = (const float*)d_in[15];
    const float* prjb = (const float*)d_in[16];
    const float* m1w  = (const float*)d_in[17];
    const float* m1b  = (const float*)d_in[18];
    const float* m2w  = (const float*)d_in[19];
    const float* m2b  = (const float*)d_in[20];
    const float* flaw = (const float*)d_in[21];
    const float* flab = (const float*)d_in[22];
    const float* flw  = (const float*)d_in[23];
    const float* flb  = (const float*)d_in[24];
    float* out = (float*)d_out;

    float *p_h, *p_mod, *p_fmod, *p_e1, *p_scb;
    __half *p_qkvh, *p_x1h, *p_aoh, *p_mhh, *p_wh;
    cudaGetSymbolAddress((void**)&p_h,   g_h);
    cudaGetSymbolAddress((void**)&p_mod, g_mod);
    cudaGetSymbolAddress((void**)&p_fmod, g_fmod);
    cudaGetSymbolAddress((void**)&p_e1,  g_e1);
    cudaGetSymbolAddress((void**)&p_scb, g_scb);
    cudaGetSymbolAddress((void**)&p_qkvh, g_qkvh);
    cudaGetSymbolAddress((void**)&p_x1h, g_x1h);
    cudaGetSymbolAddress((void**)&p_aoh, g_aoh);
    cudaGetSymbolAddress((void**)&p_mhh, g_mhh);
    cudaGetSymbolAddress((void**)&p_wh,  g_wh);

    cudaFuncSetAttribute(mma_gemm<0>, cudaFuncAttributeMaxDynamicSharedMemorySize, GSME);
    cudaFuncSetAttribute(mma_gemm<1>, cudaFuncAttributeMaxDynamicSharedMemorySize, GSME);
    cudaFuncSetAttribute(mma_gemm<2>, cudaFuncAttributeMaxDynamicSharedMemorySize, GSME);

    // weight fp16 mirrors (one launch per layer)
    for (int l = 0; l < 2; l++) {
        w2h_layer<<<(LSZ / 4 + 255) / 256, 256>>>(
            qkvw + (size_t)l * HID * QKVN, prjw + (size_t)l * HID * HID,
            m1w + (size_t)l * HID * MLPN,  m2w + (size_t)l * MLPN * HID,
            p_wh + (size_t)l * LSZ);
    }

    // conditioning path: split-K chunk 32 (temb1 inline sinusoid, chunk 16)
    smk_part_t1<<<dim3(HID / 128, 16), 128>>>(tin, tw1);
    smk_reduce<1><<<dim3(HID / 128, BATCH), 128>>>(tb1, nullptr, nullptr, p_e1, HID, 16);
    smk_part<<<dim3(HID / 128, 36), 128>>>(p_e1, tw2, HID, HID);
    smk_reduce<2><<<dim3(HID / 128, BATCH), 128>>>(tb2, ytab, y, p_scb, HID, 36);

    // layer-0 mod vectors must exist before fused patchify+LN
    smk_part<<<dim3(ADAN / 128, 36), 128>>>(p_scb, adaw, ADAN, HID);
    smk_reduce<0><<<dim3(ADAN / 128, BATCH), 128>>>(adab, nullptr, nullptr, p_mod, ADAN, 36);

    patchify_ln_kernel<<<TOK, 288>>>(x, pw, pb, pos, p_mod);

    for (int l = 0; l < 2; l++) {
        const __half* whL = p_wh + (size_t)l * LSZ;
        if (l > 0) {
            smk_part<<<dim3(ADAN / 128, 36), 128>>>(p_scb, adaw + (size_t)l * HID * ADAN, ADAN, HID);
            smk_reduce<0><<<dim3(ADAN / 128, BATCH), 128>>>(
                adab + (size_t)l * ADAN, nullptr, nullptr, p_mod, ADAN, 36);
            ln_mod_kernel<<<TOK, 288>>>(p_mod + 0, p_mod + HID, ADAN);
        }
        mma_gemm<0><<<dim3(QKVN / 128, TOK / 128), 256, GSME>>>(
            p_x1h, whL + OFF_QKV, qkvb + (size_t)l * QKVN, p_qkvh, nullptr, 0, QKVN, HID);
        attn_kernel<<<TOK, 256>>>();
        mma_gemm<2><<<dim3(HID / 128, TOK / 128), 256, GSME>>>(
            p_aoh, whL + OFF_PROJ, prjb + (size_t)l * HID, p_h, p_mod + 2 * HID, ADAN, HID, HID);

        ln_mod_kernel<<<TOK, 288>>>(p_mod + 3 * HID, p_mod + 4 * HID, ADAN);
        mma_gemm<1><<<dim3(MLPN / 128, TOK / 128), 256, GSME>>>(
            p_x1h, whL + OFF_M1, m1b + (size_t)l * MLPN, p_mhh, nullptr, 0, MLPN, HID);
        mma_gemm<2><<<dim3(HID / 128, TOK / 128), 256, GSME>>>(
            p_mhh, whL + OFF_M2, m2b + (size_t)l * HID, p_h, p_mod + 5 * HID, ADAN, HID, MLPN);
    }

    smk_part<<<dim3(2304 / 128, 36), 128>>>(p_scb, flaw, 2304, HID);
    smk_reduce<0><<<dim3(2304 / 128, BATCH), 128>>>(flab, nullptr, nullptr, p_fmod, 2304, 36);
    final2_kernel<<<TOK, 288>>>(p_fmod, flw, flb, out);

    (void)in_sizes; (void)n_in; (void)out_size;
}